// round 1
// baseline (speedup 1.0000x reference)
#include <cuda_runtime.h>
#include <stdint.h>
#include <stddef.h>

#define BB 128
#define NN 2048
#define EE 16384
#define HH 64
#define CH 16

// scratch (static device globals; no runtime allocation)
__device__ float g_dis[BB * NN];
__device__ float g_norm[BB * EE];
__device__ int   g_n[BB];
__device__ float g_z[(size_t)BB * NN * HH];   // pre-GEMM aggregated features
__device__ float g_h[(size_t)BB * NN * HH];   // layer outputs (h1 then h2)

// node_mask dtype hedge: rows are prefix masks with n >= 1024, so element 1 is
// always "true". If stored as 1-byte bool, byte[1]==1. If stored as int32 or
// float32 (4-byte elems), byte[1]==0. In the 4-byte case, reading the 32-bit
// word and testing !=0 is correct for both int32 and float32 bit patterns.
__device__ __forceinline__ bool mask_is_wide(const unsigned char* m) {
    return m[1] == 0;
}
__device__ __forceinline__ bool mask_at(const unsigned char* m, bool wide, size_t idx) {
    return wide ? (((const int*)m)[idx] != 0) : (m[idx] != 0);
}

// ---------------------------------------------------------------------------
// K0: per-batch degree, dis = rsqrt(deg), per-edge norm, node count n
// ---------------------------------------------------------------------------
__global__ void k_prep(const int* __restrict__ ei, const unsigned char* __restrict__ msk) {
    __shared__ int   sdeg[NN];
    __shared__ float sdis[NN];
    __shared__ int   s_n;
    const int b = blockIdx.x;
    const bool wide = mask_is_wide(msk);
    const size_t mb = (size_t)b * NN;
    const int* src = ei + (size_t)b * 2 * EE;
    const int* dst = src + EE;

    if (threadIdx.x == 0) s_n = 0;
    int cnt = 0;
    for (int i = threadIdx.x; i < NN; i += blockDim.x) {
        sdeg[i] = 0;
        cnt += mask_at(msk, wide, mb + i) ? 1 : 0;
    }
    __syncthreads();
    atomicAdd(&s_n, cnt);

    for (int e = threadIdx.x; e < EE; e += blockDim.x) {
        int s = src[e], d = dst[e];
        if (mask_at(msk, wide, mb + s) && mask_at(msk, wide, mb + d))
            atomicAdd(&sdeg[d], 1);
    }
    __syncthreads();
    for (int i = threadIdx.x; i < NN; i += blockDim.x) {
        float dg = (float)sdeg[i] + (mask_at(msk, wide, mb + i) ? 1.f : 0.f);
        float di = (dg > 0.f) ? rsqrtf(dg) : 0.f;
        sdis[i] = di;
        g_dis[mb + i] = di;
    }
    __syncthreads();
    for (int e = threadIdx.x; e < EE; e += blockDim.x) {
        int s = src[e], d = dst[e];
        bool v = mask_at(msk, wide, mb + s) && mask_at(msk, wide, mb + d);
        g_norm[(size_t)b * EE + e] = v ? sdis[s] * sdis[d] : 0.f;
    }
    if (threadIdx.x == 0) g_n[b] = s_n;
}

// ---------------------------------------------------------------------------
// K1: sparse aggregation on RAW features:
//   z[i] = sum_e(dst==i) norm[e]*h[src[e]] + dis[i]^2 * mask[i] * h[i]
// One CTA per (batch, 16-channel chunk); smem accumulator over all N nodes.
// ---------------------------------------------------------------------------
template <int F>
__global__ void k_agg(const float* __restrict__ xin, const int* __restrict__ ei,
                      const unsigned char* __restrict__ msk) {
    extern __shared__ float sagg[];  // NN * CH floats = 128 KB
    const int b = blockIdx.x, c = blockIdx.y;
    const bool wide = mask_is_wide(msk);
    const size_t mb = (size_t)b * NN;
    const float* hin = (F == 32) ? xin : (const float*)g_h;
    const float* hb  = hin + (size_t)b * NN * F + c * CH;

    // init with self-loop term
    for (int i = threadIdx.x; i < NN; i += blockDim.x) {
        float di = g_dis[mb + i];
        float s  = di * di * (mask_at(msk, wide, mb + i) ? 1.f : 0.f);
        const float4* h4 = (const float4*)(hb + (size_t)i * F);
        float4* a4 = (float4*)(sagg + i * CH);
        float4 v0 = h4[0], v1 = h4[1], v2 = h4[2], v3 = h4[3];
        a4[0] = make_float4(s * v0.x, s * v0.y, s * v0.z, s * v0.w);
        a4[1] = make_float4(s * v1.x, s * v1.y, s * v1.z, s * v1.w);
        a4[2] = make_float4(s * v2.x, s * v2.y, s * v2.z, s * v2.w);
        a4[3] = make_float4(s * v3.x, s * v3.y, s * v3.z, s * v3.w);
    }
    __syncthreads();

    // half-warp per edge, unroll 8 for memory-level parallelism
    const int hw = threadIdx.x >> 4;      // 0..31
    const int lane = threadIdx.x & 15;    // channel within chunk
    const int* src = ei + (size_t)b * 2 * EE;
    const int* dst = src + EE;
    const float* nrm = g_norm + (size_t)b * EE;

    for (int e = hw; e < EE; e += 32 * 8) {
        float val[8];
        int dd[8];
#pragma unroll
        for (int k = 0; k < 8; k++) {
            int ee = e + 32 * k;
            int s = src[ee];
            dd[k] = dst[ee];
            val[k] = nrm[ee] * hb[(size_t)s * F + lane];
        }
#pragma unroll
        for (int k = 0; k < 8; k++)
            atomicAdd(&sagg[dd[k] * CH + lane], val[k]);
    }
    __syncthreads();

    float* z = g_z + (size_t)b * NN * F + c * CH;
    for (int i = threadIdx.x; i < NN; i += blockDim.x) {
        const float4* a4 = (const float4*)(sagg + i * CH);
        float4* z4 = (float4*)(z + (size_t)i * F);
        z4[0] = a4[0]; z4[1] = a4[1]; z4[2] = a4[2]; z4[3] = a4[3];
    }
}

// ---------------------------------------------------------------------------
// K2: dense GEMM + bias + node-mask + relu:
//   h[i][:] = relu((z[i][:] @ W + bias) * mask[i])
// 128 nodes per block, 128 threads, each thread 4 nodes x 16 channels.
// ---------------------------------------------------------------------------
template <int F>
__global__ __launch_bounds__(128) void k_gemm(const float* __restrict__ W,
                                              const float* __restrict__ bias,
                                              const unsigned char* __restrict__ msk) {
    extern __shared__ float sm[];
    float* sW  = sm;                     // F * 64
    float* szt = sW + F * 64;            // 128 * (F+1), padded vs bank conflicts
    float* sb  = szt + 128 * (F + 1);    // 64
    const int t = threadIdx.x;
    const bool wide = mask_is_wide(msk);

    for (int i = t; i < F * 64; i += 128) sW[i] = W[i];
    if (t < 64) sb[t] = bias[t];
    const float* zg = g_z + (size_t)blockIdx.x * 128 * F;
    for (int i = t; i < 128 * F; i += 128) {
        int r = i / F, cc = i % F;       // F is a power of two
        szt[r * (F + 1) + cc] = zg[i];
    }
    __syncthreads();

    const int cg = t & 3;    // 16-channel group
    const int ng = t >> 2;   // node slot 0..31
    float acc[4][16];
#pragma unroll
    for (int k = 0; k < 4; k++)
#pragma unroll
        for (int j = 0; j < 16; j++) acc[k][j] = 0.f;

    for (int f = 0; f < F; f++) {
        float zv[4];
#pragma unroll
        for (int k = 0; k < 4; k++) zv[k] = szt[(ng + 32 * k) * (F + 1) + f];
        float wv[16];
        const float4* wr = (const float4*)(sW + f * 64 + cg * 16);
        *(float4*)&wv[0]  = wr[0];
        *(float4*)&wv[4]  = wr[1];
        *(float4*)&wv[8]  = wr[2];
        *(float4*)&wv[12] = wr[3];
#pragma unroll
        for (int k = 0; k < 4; k++)
#pragma unroll
            for (int j = 0; j < 16; j++) acc[k][j] += zv[k] * wv[j];
    }

    const size_t nodebase = (size_t)blockIdx.x * 128;
#pragma unroll
    for (int k = 0; k < 4; k++) {
        size_t gn = nodebase + ng + 32 * k;
        float m = mask_at(msk, wide, gn) ? 1.f : 0.f;
        float* outp = g_h + gn * 64 + cg * 16;
#pragma unroll
        for (int q = 0; q < 4; q++) {
            float4 o;
            o.x = fmaxf((acc[k][q * 4 + 0] + sb[cg * 16 + q * 4 + 0]) * m, 0.f);
            o.y = fmaxf((acc[k][q * 4 + 1] + sb[cg * 16 + q * 4 + 1]) * m, 0.f);
            o.z = fmaxf((acc[k][q * 4 + 2] + sb[cg * 16 + q * 4 + 2]) * m, 0.f);
            o.w = fmaxf((acc[k][q * 4 + 3] + sb[cg * 16 + q * 4 + 3]) * m, 0.f);
            ((float4*)outp)[q] = o;
        }
    }
}

// ---------------------------------------------------------------------------
// K3: mean-pool over nodes + 2-layer MLP head, one CTA per batch
// ---------------------------------------------------------------------------
__global__ void k_pool(const float* __restrict__ aW1, const float* __restrict__ ab1,
                       const float* __restrict__ aW2, const float* __restrict__ ab2,
                       float* __restrict__ out) {
    __shared__ float sp[4 * 64];
    __shared__ float pooled[64];
    __shared__ float hid[64];
    const int b = blockIdx.x, t = threadIdx.x;
    const int ch = t & 63, part = t >> 6;
    const float* hbase = (const float*)g_h + (size_t)b * NN * 64;
    float s = 0.f;
    for (int i = part; i < NN; i += 4) s += hbase[(size_t)i * 64 + ch];
    sp[part * 64 + ch] = s;
    __syncthreads();
    if (t < 64) {
        float p = sp[t] + sp[64 + t] + sp[128 + t] + sp[192 + t];
        int n = g_n[b]; if (n < 1) n = 1;
        pooled[t] = p / (float)n;
    }
    __syncthreads();
    if (t < 64) {
        float a = ab1[t];
#pragma unroll
        for (int f = 0; f < 64; f++) a += pooled[f] * aW1[f * 64 + t];
        hid[t] = fmaxf(a, 0.f);
    }
    __syncthreads();
    if (t < 16) {
        float a = ab2[t];
#pragma unroll
        for (int f = 0; f < 64; f++) a += hid[f] * aW2[f * 16 + t];
        out[b * 16 + t] = a;
    }
}

// ---------------------------------------------------------------------------
extern "C" void kernel_launch(void* const* d_in, const int* in_sizes, int n_in,
                              void* d_out, int out_size) {
    const float*         x   = (const float*)d_in[0];
    const int*           ei  = (const int*)d_in[1];
    const unsigned char* msk = (const unsigned char*)d_in[2];
    const float* W1  = (const float*)d_in[3];
    const float* b1  = (const float*)d_in[4];
    const float* W2  = (const float*)d_in[5];
    const float* b2  = (const float*)d_in[6];
    const float* aW1 = (const float*)d_in[7];
    const float* ab1 = (const float*)d_in[8];
    const float* aW2 = (const float*)d_in[9];
    const float* ab2 = (const float*)d_in[10];
    float* out = (float*)d_out;

    const int aggSmem  = NN * CH * 4;                                   // 128 KB
    const int gemm32Sm = (32 * 64 + 128 * 33 + 64) * 4;                 // ~25 KB
    const int gemm64Sm = (64 * 64 + 128 * 65 + 64) * 4;                 // ~49 KB
    cudaFuncSetAttribute(k_agg<32>,  cudaFuncAttributeMaxDynamicSharedMemorySize, aggSmem);
    cudaFuncSetAttribute(k_agg<64>,  cudaFuncAttributeMaxDynamicSharedMemorySize, aggSmem);
    cudaFuncSetAttribute(k_gemm<32>, cudaFuncAttributeMaxDynamicSharedMemorySize, gemm32Sm);
    cudaFuncSetAttribute(k_gemm<64>, cudaFuncAttributeMaxDynamicSharedMemorySize, gemm64Sm);

    k_prep<<<BB, 256>>>(ei, msk);
    // layer 1: aggregate raw x (F=32), then GEMM with W1 -> h1
    k_agg<32><<<dim3(BB, 2), 512, aggSmem>>>(x, ei, msk);
    k_gemm<32><<<(BB * NN) / 128, 128, gemm32Sm>>>(W1, b1, msk);
    // layer 2: aggregate h1 (F=64), then GEMM with W2 -> h2
    k_agg<64><<<dim3(BB, 4), 512, aggSmem>>>(x, ei, msk);
    k_gemm<64><<<(BB * NN) / 128, 128, gemm64Sm>>>(W2, b2, msk);
    // pool + MLP head
    k_pool<<<BB, 256>>>(aW1, ab1, aW2, ab2, out);
}

// round 2
// speedup vs baseline: 1.0080x; 1.0080x over previous
#include <cuda_runtime.h>
#include <stdint.h>
#include <stddef.h>

#define BB 128
#define NN 2048
#define EE 16384
#define HH 64
#define CH 16

// scratch (static device globals; no runtime allocation)
__device__ float g_dis[BB * NN];
__device__ float g_norm[BB * EE];
__device__ int   g_n[BB];
__device__ float g_z[(size_t)BB * NN * HH];   // pre-GEMM aggregated features
__device__ float g_h[(size_t)BB * NN * HH];   // layer outputs (h1 then h2)

// node_mask dtype hedge: rows are prefix masks with n >= 1024, so element 1 is
// always "true". If stored as 1-byte bool, byte[1]==1. If stored as int32 or
// float32 (4-byte elems), byte[1]==0. In the 4-byte case, reading the 32-bit
// word and testing !=0 is correct for both int32 and float32 bit patterns.
__device__ __forceinline__ bool mask_is_wide(const unsigned char* m) {
    return m[1] == 0;
}
__device__ __forceinline__ bool mask_at(const unsigned char* m, bool wide, size_t idx) {
    return wide ? (((const int*)m)[idx] != 0) : (m[idx] != 0);
}

// ---------------------------------------------------------------------------
// K0: per-batch degree, dis = rsqrt(deg), per-edge norm, node count n
// ---------------------------------------------------------------------------
__global__ void k_prep(const int* __restrict__ ei, const unsigned char* __restrict__ msk) {
    __shared__ int   sdeg[NN];
    __shared__ float sdis[NN];
    __shared__ int   s_n;
    const int b = blockIdx.x;
    const bool wide = mask_is_wide(msk);
    const size_t mb = (size_t)b * NN;
    const int* src = ei + (size_t)b * 2 * EE;
    const int* dst = src + EE;

    if (threadIdx.x == 0) s_n = 0;
    int cnt = 0;
    for (int i = threadIdx.x; i < NN; i += blockDim.x) {
        sdeg[i] = 0;
        cnt += mask_at(msk, wide, mb + i) ? 1 : 0;
    }
    __syncthreads();
    atomicAdd(&s_n, cnt);

    for (int e = threadIdx.x; e < EE; e += blockDim.x) {
        int s = src[e], d = dst[e];
        if (mask_at(msk, wide, mb + s) && mask_at(msk, wide, mb + d))
            atomicAdd(&sdeg[d], 1);
    }
    __syncthreads();
    for (int i = threadIdx.x; i < NN; i += blockDim.x) {
        float dg = (float)sdeg[i] + (mask_at(msk, wide, mb + i) ? 1.f : 0.f);
        float di = (dg > 0.f) ? rsqrtf(dg) : 0.f;
        sdis[i] = di;
        g_dis[mb + i] = di;
    }
    __syncthreads();
    for (int e = threadIdx.x; e < EE; e += blockDim.x) {
        int s = src[e], d = dst[e];
        bool v = mask_at(msk, wide, mb + s) && mask_at(msk, wide, mb + d);
        g_norm[(size_t)b * EE + e] = v ? sdis[s] * sdis[d] : 0.f;
    }
    if (threadIdx.x == 0) g_n[b] = s_n;
}

// ---------------------------------------------------------------------------
// K1: sparse aggregation on RAW features:
//   z[i] = sum_e(dst==i) norm[e]*h[src[e]] + dis[i]^2 * mask[i] * h[i]
// One CTA per (batch, 16-channel chunk); smem accumulator over all N nodes.
// ---------------------------------------------------------------------------
template <int F>
__global__ void k_agg(const float* __restrict__ xin, const int* __restrict__ ei,
                      const unsigned char* __restrict__ msk) {
    extern __shared__ float sagg[];  // NN * CH floats = 128 KB
    const int b = blockIdx.x, c = blockIdx.y;
    const bool wide = mask_is_wide(msk);
    const size_t mb = (size_t)b * NN;
    const float* hin = (F == 32) ? xin : (const float*)g_h;
    const float* hb  = hin + (size_t)b * NN * F + c * CH;

    // init with self-loop term
    for (int i = threadIdx.x; i < NN; i += blockDim.x) {
        float di = g_dis[mb + i];
        float s  = di * di * (mask_at(msk, wide, mb + i) ? 1.f : 0.f);
        const float4* h4 = (const float4*)(hb + (size_t)i * F);
        float4* a4 = (float4*)(sagg + i * CH);
        float4 v0 = h4[0], v1 = h4[1], v2 = h4[2], v3 = h4[3];
        a4[0] = make_float4(s * v0.x, s * v0.y, s * v0.z, s * v0.w);
        a4[1] = make_float4(s * v1.x, s * v1.y, s * v1.z, s * v1.w);
        a4[2] = make_float4(s * v2.x, s * v2.y, s * v2.z, s * v2.w);
        a4[3] = make_float4(s * v3.x, s * v3.y, s * v3.z, s * v3.w);
    }
    __syncthreads();

    // half-warp per edge, unroll 8 for memory-level parallelism
    const int hw = threadIdx.x >> 4;      // 0..31
    const int lane = threadIdx.x & 15;    // channel within chunk
    const int* src = ei + (size_t)b * 2 * EE;
    const int* dst = src + EE;
    const float* nrm = g_norm + (size_t)b * EE;

    for (int e = hw; e < EE; e += 32 * 8) {
        float val[8];
        int dd[8];
#pragma unroll
        for (int k = 0; k < 8; k++) {
            int ee = e + 32 * k;
            int s = src[ee];
            dd[k] = dst[ee];
            val[k] = nrm[ee] * hb[(size_t)s * F + lane];
        }
#pragma unroll
        for (int k = 0; k < 8; k++)
            atomicAdd(&sagg[dd[k] * CH + lane], val[k]);
    }
    __syncthreads();

    float* z = g_z + (size_t)b * NN * F + c * CH;
    for (int i = threadIdx.x; i < NN; i += blockDim.x) {
        const float4* a4 = (const float4*)(sagg + i * CH);
        float4* z4 = (float4*)(z + (size_t)i * F);
        z4[0] = a4[0]; z4[1] = a4[1]; z4[2] = a4[2]; z4[3] = a4[3];
    }
}

// ---------------------------------------------------------------------------
// K2: dense GEMM + bias + node-mask + relu:
//   h[i][:] = relu((z[i][:] @ W + bias) * mask[i])
// 128 nodes per block, 128 threads, each thread 4 nodes x 16 channels.
// ---------------------------------------------------------------------------
template <int F>
__global__ __launch_bounds__(128) void k_gemm(const float* __restrict__ W,
                                              const float* __restrict__ bias,
                                              const unsigned char* __restrict__ msk) {
    extern __shared__ float sm[];
    float* sW  = sm;                     // F * 64
    float* szt = sW + F * 64;            // 128 * (F+1), padded vs bank conflicts
    float* sb  = szt + 128 * (F + 1);    // 64
    const int t = threadIdx.x;
    const bool wide = mask_is_wide(msk);

    for (int i = t; i < F * 64; i += 128) sW[i] = W[i];
    if (t < 64) sb[t] = bias[t];
    const float* zg = g_z + (size_t)blockIdx.x * 128 * F;
    for (int i = t; i < 128 * F; i += 128) {
        int r = i / F, cc = i % F;       // F is a power of two
        szt[r * (F + 1) + cc] = zg[i];
    }
    __syncthreads();

    const int cg = t & 3;    // 16-channel group
    const int ng = t >> 2;   // node slot 0..31
    float acc[4][16];
#pragma unroll
    for (int k = 0; k < 4; k++)
#pragma unroll
        for (int j = 0; j < 16; j++) acc[k][j] = 0.f;

    for (int f = 0; f < F; f++) {
        float zv[4];
#pragma unroll
        for (int k = 0; k < 4; k++) zv[k] = szt[(ng + 32 * k) * (F + 1) + f];
        float wv[16];
        const float4* wr = (const float4*)(sW + f * 64 + cg * 16);
        *(float4*)&wv[0]  = wr[0];
        *(float4*)&wv[4]  = wr[1];
        *(float4*)&wv[8]  = wr[2];
        *(float4*)&wv[12] = wr[3];
#pragma unroll
        for (int k = 0; k < 4; k++)
#pragma unroll
            for (int j = 0; j < 16; j++) acc[k][j] += zv[k] * wv[j];
    }

    const size_t nodebase = (size_t)blockIdx.x * 128;
#pragma unroll
    for (int k = 0; k < 4; k++) {
        size_t gn = nodebase + ng + 32 * k;
        float m = mask_at(msk, wide, gn) ? 1.f : 0.f;
        float* outp = g_h + gn * 64 + cg * 16;
#pragma unroll
        for (int q = 0; q < 4; q++) {
            float4 o;
            o.x = fmaxf((acc[k][q * 4 + 0] + sb[cg * 16 + q * 4 + 0]) * m, 0.f);
            o.y = fmaxf((acc[k][q * 4 + 1] + sb[cg * 16 + q * 4 + 1]) * m, 0.f);
            o.z = fmaxf((acc[k][q * 4 + 2] + sb[cg * 16 + q * 4 + 2]) * m, 0.f);
            o.w = fmaxf((acc[k][q * 4 + 3] + sb[cg * 16 + q * 4 + 3]) * m, 0.f);
            ((float4*)outp)[q] = o;
        }
    }
}

// ---------------------------------------------------------------------------
// K3: mean-pool over nodes + 2-layer MLP head, one CTA per batch
// ---------------------------------------------------------------------------
__global__ void k_pool(const float* __restrict__ aW1, const float* __restrict__ ab1,
                       const float* __restrict__ aW2, const float* __restrict__ ab2,
                       float* __restrict__ out) {
    __shared__ float sp[4 * 64];
    __shared__ float pooled[64];
    __shared__ float hid[64];
    const int b = blockIdx.x, t = threadIdx.x;
    const int ch = t & 63, part = t >> 6;
    const float* hbase = (const float*)g_h + (size_t)b * NN * 64;
    float s = 0.f;
    for (int i = part; i < NN; i += 4) s += hbase[(size_t)i * 64 + ch];
    sp[part * 64 + ch] = s;
    __syncthreads();
    if (t < 64) {
        float p = sp[t] + sp[64 + t] + sp[128 + t] + sp[192 + t];
        int n = g_n[b]; if (n < 1) n = 1;
        pooled[t] = p / (float)n;
    }
    __syncthreads();
    if (t < 64) {
        float a = ab1[t];
#pragma unroll
        for (int f = 0; f < 64; f++) a += pooled[f] * aW1[f * 64 + t];
        hid[t] = fmaxf(a, 0.f);
    }
    __syncthreads();
    if (t < 16) {
        float a = ab2[t];
#pragma unroll
        for (int f = 0; f < 64; f++) a += hid[f] * aW2[f * 16 + t];
        out[b * 16 + t] = a;
    }
}

// ---------------------------------------------------------------------------
extern "C" void kernel_launch(void* const* d_in, const int* in_sizes, int n_in,
                              void* d_out, int out_size) {
    const float*         x   = (const float*)d_in[0];
    const int*           ei  = (const int*)d_in[1];
    const unsigned char* msk = (const unsigned char*)d_in[2];
    const float* W1  = (const float*)d_in[3];
    const float* b1  = (const float*)d_in[4];
    const float* W2  = (const float*)d_in[5];
    const float* b2  = (const float*)d_in[6];
    const float* aW1 = (const float*)d_in[7];
    const float* ab1 = (const float*)d_in[8];
    const float* aW2 = (const float*)d_in[9];
    const float* ab2 = (const float*)d_in[10];
    float* out = (float*)d_out;

    const int aggSmem  = NN * CH * 4;                                   // 128 KB
    const int gemm32Sm = (32 * 64 + 128 * 33 + 64) * 4;                 // ~25 KB
    const int gemm64Sm = (64 * 64 + 128 * 65 + 64) * 4;                 // ~49 KB
    cudaFuncSetAttribute(k_agg<32>,  cudaFuncAttributeMaxDynamicSharedMemorySize, aggSmem);
    cudaFuncSetAttribute(k_agg<64>,  cudaFuncAttributeMaxDynamicSharedMemorySize, aggSmem);
    cudaFuncSetAttribute(k_gemm<32>, cudaFuncAttributeMaxDynamicSharedMemorySize, gemm32Sm);
    cudaFuncSetAttribute(k_gemm<64>, cudaFuncAttributeMaxDynamicSharedMemorySize, gemm64Sm);

    k_prep<<<BB, 256>>>(ei, msk);
    // layer 1: aggregate raw x (F=32), then GEMM with W1 -> h1
    k_agg<32><<<dim3(BB, 2), 512, aggSmem>>>(x, ei, msk);
    k_gemm<32><<<(BB * NN) / 128, 128, gemm32Sm>>>(W1, b1, msk);
    // layer 2: aggregate h1 (F=64), then GEMM with W2 -> h2
    k_agg<64><<<dim3(BB, 4), 512, aggSmem>>>(x, ei, msk);
    k_gemm<64><<<(BB * NN) / 128, 128, gemm64Sm>>>(W2, b2, msk);
    // pool + MLP head
    k_pool<<<BB, 256>>>(aW1, ab1, aW2, ab2, out);
}

// round 3
// speedup vs baseline: 1.8352x; 1.8206x over previous
#include <cuda_runtime.h>
#include <stdint.h>
#include <stddef.h>

#define BB 128
#define NN 2048
#define EE 16384
#define HH 64

// scratch (static device globals; no runtime allocation)
__device__ float  g_dis[BB * NN];
__device__ int    g_n[BB];
__device__ int    g_rowptr[BB * (NN + 1)];
__device__ float2 g_csr[(size_t)BB * EE];     // .x = src (int bits), .y = norm
__device__ float  g_z[(size_t)BB * NN * HH];  // pre-GEMM aggregated features
__device__ float  g_h[(size_t)BB * NN * HH];  // layer outputs (h1 then h2)

// node_mask dtype hedge: rows are prefix masks with n >= 1024, so element 1 is
// always "true". If stored as 1-byte bool, byte[1]==1. If stored as int32 or
// float32 (4-byte elems), byte[1]==0.
__device__ __forceinline__ bool mask_is_wide(const unsigned char* m) {
    return m[1] == 0;
}
__device__ __forceinline__ bool mask_at(const unsigned char* m, bool wide, size_t idx) {
    return wide ? (((const int*)m)[idx] != 0) : (m[idx] != 0);
}

// ---------------------------------------------------------------------------
// K0: per-batch degree, dis = rsqrt(deg), CSR build (valid edges only, with
// per-edge norm precomputed), node count n. One 512-thread CTA per batch.
// ---------------------------------------------------------------------------
__global__ __launch_bounds__(512) void k_prep(const int* __restrict__ ei,
                                              const unsigned char* __restrict__ msk) {
    __shared__ int   sdeg[NN];
    __shared__ float sdis[NN];
    __shared__ int   srow[NN];
    __shared__ int   scur[NN];
    __shared__ int   ssum[512];
    __shared__ unsigned char smask[NN];
    __shared__ int   s_n;

    const int b = blockIdx.x;
    const int t = threadIdx.x;
    const bool wide = mask_is_wide(msk);
    const size_t mb = (size_t)b * NN;
    const int* src = ei + (size_t)b * 2 * EE;
    const int* dst = src + EE;

    if (t == 0) s_n = 0;
    int cnt = 0;
    for (int i = t; i < NN; i += 512) {
        sdeg[i] = 0;
        unsigned char m = mask_at(msk, wide, mb + i) ? 1 : 0;
        smask[i] = m;
        cnt += m;
    }
    __syncthreads();
    atomicAdd(&s_n, cnt);

    // degree of valid edges
    for (int e = t; e < EE; e += 512) {
        int s = src[e], d = dst[e];
        if (smask[s] & smask[d]) atomicAdd(&sdeg[d], 1);
    }
    __syncthreads();

    // dis = rsqrt(deg + self)
    for (int i = t; i < NN; i += 512) {
        float dg = (float)sdeg[i] + (float)smask[i];
        sdis[i] = (dg > 0.f) ? rsqrtf(dg) : 0.f;
        g_dis[mb + i] = sdis[i];
    }
    __syncthreads();

    // exclusive scan of sdeg -> srow (each thread owns 4 consecutive entries)
    {
        int base = t * 4;
        int a0 = sdeg[base], a1 = sdeg[base + 1], a2 = sdeg[base + 2], a3 = sdeg[base + 3];
        int tot = a0 + a1 + a2 + a3;
        ssum[t] = tot;
        __syncthreads();
#pragma unroll
        for (int off = 1; off < 512; off <<= 1) {
            int v = ssum[t];
            int u = (t >= off) ? ssum[t - off] : 0;
            __syncthreads();
            ssum[t] = v + u;
            __syncthreads();
        }
        int excl = ssum[t] - tot;
        srow[base]     = excl;
        srow[base + 1] = excl + a0;
        srow[base + 2] = excl + a0 + a1;
        srow[base + 3] = excl + a0 + a1 + a2;
        scur[base]     = srow[base];
        scur[base + 1] = srow[base + 1];
        scur[base + 2] = srow[base + 2];
        scur[base + 3] = srow[base + 3];
    }
    __syncthreads();

    // write rowptr
    int* rp = g_rowptr + (size_t)b * (NN + 1);
    for (int i = t; i < NN; i += 512) rp[i] = srow[i];
    if (t == 511) {
        rp[NN] = ssum[511];
        g_n[b] = s_n;
    }
    __syncthreads();

    // scatter valid edges with norm
    float2* csr = g_csr + (size_t)b * EE;
    for (int e = t; e < EE; e += 512) {
        int s = src[e], d = dst[e];
        if (smask[s] & smask[d]) {
            float nm = sdis[s] * sdis[d];
            int pos = atomicAdd(&scur[d], 1);
            float2 v;
            v.x = __int_as_float(s);
            v.y = nm;
            csr[pos] = v;
        }
    }
}

// ---------------------------------------------------------------------------
// K1: CSR gather aggregation:
//   z[i] = dis[i]^2 * h[i] + sum_{e in row(i)} norm[e] * h[src[e]]
// Warp per node (NPW nodes per warp), lanes parallel over channels. No atomics.
// ---------------------------------------------------------------------------
#define NPW 4
template <int F>
__global__ __launch_bounds__(256) void k_agg(const float* __restrict__ xin) {
    const int b = blockIdx.y;
    const int warp = threadIdx.x >> 5;  // 0..7
    const int lane = threadIdx.x & 31;
    const int iBase = (blockIdx.x * 8 + warp) * NPW;

    const float* hb = (F == 32) ? xin + (size_t)b * NN * 32
                                : (const float*)g_h + (size_t)b * NN * 64;
    const float2* csr = g_csr + (size_t)b * EE;
    const int* rp = g_rowptr + (size_t)b * (NN + 1);
    const float* dis = g_dis + (size_t)b * NN;
    float* z = g_z + (size_t)b * NN * F;

#pragma unroll
    for (int k = 0; k < NPW; k++) {
        const int i = iBase + k;
        const int r0 = rp[i];
        const int r1 = rp[i + 1];
        const float di = dis[i];
        const float selfs = di * di;  // zero when node unmasked (dis==0)

        if (F == 64) {
            const float2* hrow = (const float2*)(hb + (size_t)i * 64);
            float2 hv = hrow[lane];
            float2 acc = make_float2(selfs * hv.x, selfs * hv.y);
            int e = r0;
            for (; e + 1 < r1; e += 2) {
                float2 c0 = csr[e], c1 = csr[e + 1];
                int s0 = __float_as_int(c0.x), s1 = __float_as_int(c1.x);
                float2 g0 = ((const float2*)(hb + (size_t)s0 * 64))[lane];
                float2 g1 = ((const float2*)(hb + (size_t)s1 * 64))[lane];
                acc.x += c0.y * g0.x + c1.y * g1.x;
                acc.y += c0.y * g0.y + c1.y * g1.y;
            }
            if (e < r1) {
                float2 c0 = csr[e];
                int s0 = __float_as_int(c0.x);
                float2 g0 = ((const float2*)(hb + (size_t)s0 * 64))[lane];
                acc.x += c0.y * g0.x;
                acc.y += c0.y * g0.y;
            }
            ((float2*)(z + (size_t)i * 64))[lane] = acc;
        } else {
            float acc = selfs * hb[(size_t)i * 32 + lane];
            int e = r0;
            for (; e + 1 < r1; e += 2) {
                float2 c0 = csr[e], c1 = csr[e + 1];
                int s0 = __float_as_int(c0.x), s1 = __float_as_int(c1.x);
                acc += c0.y * hb[(size_t)s0 * 32 + lane]
                     + c1.y * hb[(size_t)s1 * 32 + lane];
            }
            if (e < r1) {
                float2 c0 = csr[e];
                int s0 = __float_as_int(c0.x);
                acc += c0.y * hb[(size_t)s0 * 32 + lane];
            }
            z[(size_t)i * 32 + lane] = acc;
        }
    }
}

// ---------------------------------------------------------------------------
// K2: dense GEMM + bias + node-mask + relu:
//   h[i][:] = relu((z[i][:] @ W + bias) * mask[i])
// 128 nodes per block, 128 threads, each thread 4 nodes x 16 channels.
// ---------------------------------------------------------------------------
template <int F>
__global__ __launch_bounds__(128) void k_gemm(const float* __restrict__ W,
                                              const float* __restrict__ bias,
                                              const unsigned char* __restrict__ msk) {
    extern __shared__ float sm[];
    float* sW  = sm;                     // F * 64
    float* szt = sW + F * 64;            // 128 * (F+1), padded vs bank conflicts
    float* sb  = szt + 128 * (F + 1);    // 64
    const int t = threadIdx.x;
    const bool wide = mask_is_wide(msk);

    for (int i = t; i < F * 64; i += 128) sW[i] = W[i];
    if (t < 64) sb[t] = bias[t];
    const float* zg = g_z + (size_t)blockIdx.x * 128 * F;
    for (int i = t; i < 128 * F; i += 128) {
        int r = i / F, cc = i % F;
        szt[r * (F + 1) + cc] = zg[i];
    }
    __syncthreads();

    const int cg = t & 3;
    const int ng = t >> 2;
    float acc[4][16];
#pragma unroll
    for (int k = 0; k < 4; k++)
#pragma unroll
        for (int j = 0; j < 16; j++) acc[k][j] = 0.f;

    for (int f = 0; f < F; f++) {
        float zv[4];
#pragma unroll
        for (int k = 0; k < 4; k++) zv[k] = szt[(ng + 32 * k) * (F + 1) + f];
        float wv[16];
        const float4* wr = (const float4*)(sW + f * 64 + cg * 16);
        *(float4*)&wv[0]  = wr[0];
        *(float4*)&wv[4]  = wr[1];
        *(float4*)&wv[8]  = wr[2];
        *(float4*)&wv[12] = wr[3];
#pragma unroll
        for (int k = 0; k < 4; k++)
#pragma unroll
            for (int j = 0; j < 16; j++) acc[k][j] += zv[k] * wv[j];
    }

    const size_t nodebase = (size_t)blockIdx.x * 128;
#pragma unroll
    for (int k = 0; k < 4; k++) {
        size_t gn = nodebase + ng + 32 * k;
        float m = mask_at(msk, wide, gn) ? 1.f : 0.f;
        float* outp = g_h + gn * 64 + cg * 16;
#pragma unroll
        for (int q = 0; q < 4; q++) {
            float4 o;
            o.x = fmaxf((acc[k][q * 4 + 0] + sb[cg * 16 + q * 4 + 0]) * m, 0.f);
            o.y = fmaxf((acc[k][q * 4 + 1] + sb[cg * 16 + q * 4 + 1]) * m, 0.f);
            o.z = fmaxf((acc[k][q * 4 + 2] + sb[cg * 16 + q * 4 + 2]) * m, 0.f);
            o.w = fmaxf((acc[k][q * 4 + 3] + sb[cg * 16 + q * 4 + 3]) * m, 0.f);
            ((float4*)outp)[q] = o;
        }
    }
}

// ---------------------------------------------------------------------------
// K3: mean-pool over nodes + 2-layer MLP head, one CTA per batch
// ---------------------------------------------------------------------------
__global__ void k_pool(const float* __restrict__ aW1, const float* __restrict__ ab1,
                       const float* __restrict__ aW2, const float* __restrict__ ab2,
                       float* __restrict__ out) {
    __shared__ float sp[4 * 64];
    __shared__ float pooled[64];
    __shared__ float hid[64];
    const int b = blockIdx.x, t = threadIdx.x;
    const int ch = t & 63, part = t >> 6;
    const float* hbase = (const float*)g_h + (size_t)b * NN * 64;
    float s = 0.f;
    for (int i = part; i < NN; i += 4) s += hbase[(size_t)i * 64 + ch];
    sp[part * 64 + ch] = s;
    __syncthreads();
    if (t < 64) {
        float p = sp[t] + sp[64 + t] + sp[128 + t] + sp[192 + t];
        int n = g_n[b]; if (n < 1) n = 1;
        pooled[t] = p / (float)n;
    }
    __syncthreads();
    if (t < 64) {
        float a = ab1[t];
#pragma unroll
        for (int f = 0; f < 64; f++) a += pooled[f] * aW1[f * 64 + t];
        hid[t] = fmaxf(a, 0.f);
    }
    __syncthreads();
    if (t < 16) {
        float a = ab2[t];
#pragma unroll
        for (int f = 0; f < 64; f++) a += hid[f] * aW2[f * 16 + t];
        out[b * 16 + t] = a;
    }
}

// ---------------------------------------------------------------------------
extern "C" void kernel_launch(void* const* d_in, const int* in_sizes, int n_in,
                              void* d_out, int out_size) {
    const float*         x   = (const float*)d_in[0];
    const int*           ei  = (const int*)d_in[1];
    const unsigned char* msk = (const unsigned char*)d_in[2];
    const float* W1  = (const float*)d_in[3];
    const float* b1  = (const float*)d_in[4];
    const float* W2  = (const float*)d_in[5];
    const float* b2  = (const float*)d_in[6];
    const float* aW1 = (const float*)d_in[7];
    const float* ab1 = (const float*)d_in[8];
    const float* aW2 = (const float*)d_in[9];
    const float* ab2 = (const float*)d_in[10];
    float* out = (float*)d_out;

    const int gemm32Sm = (32 * 64 + 128 * 33 + 64) * 4;   // ~25 KB
    const int gemm64Sm = (64 * 64 + 128 * 65 + 64) * 4;   // ~49 KB
    cudaFuncSetAttribute(k_gemm<32>, cudaFuncAttributeMaxDynamicSharedMemorySize, gemm32Sm);
    cudaFuncSetAttribute(k_gemm<64>, cudaFuncAttributeMaxDynamicSharedMemorySize, gemm64Sm);

    // prep: degrees, dis, CSR with per-edge norm (invalid edges dropped)
    k_prep<<<BB, 512>>>(ei, msk);

    const dim3 aggGrid(NN / (8 * NPW), BB);  // (64, 128)
    // layer 1: aggregate raw x (F=32), then GEMM with W1 -> h1
    k_agg<32><<<aggGrid, 256>>>(x);
    k_gemm<32><<<(BB * NN) / 128, 128, gemm32Sm>>>(W1, b1, msk);
    // layer 2: aggregate h1 (F=64), then GEMM with W2 -> h2
    k_agg<64><<<aggGrid, 256>>>(x);
    k_gemm<64><<<(BB * NN) / 128, 128, gemm64Sm>>>(W2, b2, msk);
    // pool + MLP head
    k_pool<<<BB, 256>>>(aW1, ab1, aW2, ab2, out);
}

// round 4
// speedup vs baseline: 2.6687x; 1.4542x over previous
#include <cuda_runtime.h>
#include <stdint.h>
#include <stddef.h>

#define BB 128
#define NN 2048
#define EE 16384

// scratch (static device globals; no runtime allocation)
__device__ float  g_dis[BB * NN];
__device__ int    g_n[BB];
__device__ int    g_rowptr[BB * (NN + 1)];
__device__ float2 g_csr[(size_t)BB * EE];     // .x = src (int bits), .y = norm
__device__ float  g_h[(size_t)BB * NN * 64];  // h1 (layer-1 output)
__device__ float  g_pool[BB * 64];            // pooled partial sums

// node_mask dtype hedge: rows are prefix masks with n >= 1024, so element 1 is
// always "true". If stored as 1-byte bool, byte[1]==1. If stored as int32 or
// float32 (4-byte elems), byte[1]==0.
__device__ __forceinline__ bool mask_is_wide(const unsigned char* m) {
    return m[1] == 0;
}
__device__ __forceinline__ bool mask_at(const unsigned char* m, bool wide, size_t idx) {
    return wide ? (((const int*)m)[idx] != 0) : (m[idx] != 0);
}

// ---------------------------------------------------------------------------
// K0: per-batch degree, dis = rsqrt(deg), CSR build (valid edges only, with
// per-edge norm precomputed), node count n, zero pool accumulators.
// One 512-thread CTA per batch. Edge lists read as int4.
// ---------------------------------------------------------------------------
__global__ __launch_bounds__(512) void k_prep(const int* __restrict__ ei,
                                              const unsigned char* __restrict__ msk) {
    __shared__ int   sdeg[NN];
    __shared__ float sdis[NN];
    __shared__ int   srow[NN];
    __shared__ int   scur[NN];
    __shared__ int   ssum[512];
    __shared__ unsigned char smask[NN];
    __shared__ int   s_n;

    const int b = blockIdx.x;
    const int t = threadIdx.x;
    const bool wide = mask_is_wide(msk);
    const size_t mb = (size_t)b * NN;
    const int* src = ei + (size_t)b * 2 * EE;
    const int* dst = src + EE;
    const int4* src4 = (const int4*)src;
    const int4* dst4 = (const int4*)dst;

    if (t == 0) s_n = 0;
    if (t < 64) g_pool[b * 64 + t] = 0.f;
    int cnt = 0;
    for (int i = t; i < NN; i += 512) {
        sdeg[i] = 0;
        unsigned char m = mask_at(msk, wide, mb + i) ? 1 : 0;
        smask[i] = m;
        cnt += m;
    }
    __syncthreads();
    atomicAdd(&s_n, cnt);

    // degree of valid edges (4 edges per thread-iter)
    for (int e4 = t; e4 < EE / 4; e4 += 512) {
        int4 s = src4[e4], d = dst4[e4];
        if (smask[s.x] & smask[d.x]) atomicAdd(&sdeg[d.x], 1);
        if (smask[s.y] & smask[d.y]) atomicAdd(&sdeg[d.y], 1);
        if (smask[s.z] & smask[d.z]) atomicAdd(&sdeg[d.z], 1);
        if (smask[s.w] & smask[d.w]) atomicAdd(&sdeg[d.w], 1);
    }
    __syncthreads();

    // dis = rsqrt(deg + self)
    for (int i = t; i < NN; i += 512) {
        float dg = (float)sdeg[i] + (float)smask[i];
        sdis[i] = (dg > 0.f) ? rsqrtf(dg) : 0.f;
        g_dis[mb + i] = sdis[i];
    }
    __syncthreads();

    // exclusive scan of sdeg -> srow (each thread owns 4 consecutive entries)
    {
        int base = t * 4;
        int a0 = sdeg[base], a1 = sdeg[base + 1], a2 = sdeg[base + 2], a3 = sdeg[base + 3];
        int tot = a0 + a1 + a2 + a3;
        ssum[t] = tot;
        __syncthreads();
#pragma unroll
        for (int off = 1; off < 512; off <<= 1) {
            int v = ssum[t];
            int u = (t >= off) ? ssum[t - off] : 0;
            __syncthreads();
            ssum[t] = v + u;
            __syncthreads();
        }
        int excl = ssum[t] - tot;
        srow[base]     = excl;
        srow[base + 1] = excl + a0;
        srow[base + 2] = excl + a0 + a1;
        srow[base + 3] = excl + a0 + a1 + a2;
        scur[base]     = srow[base];
        scur[base + 1] = srow[base + 1];
        scur[base + 2] = srow[base + 2];
        scur[base + 3] = srow[base + 3];
    }
    __syncthreads();

    // write rowptr
    int* rp = g_rowptr + (size_t)b * (NN + 1);
    for (int i = t; i < NN; i += 512) rp[i] = srow[i];
    if (t == 511) {
        rp[NN] = ssum[511];
        g_n[b] = s_n;
    }
    __syncthreads();

    // scatter valid edges with norm
    float2* csr = g_csr + (size_t)b * EE;
    for (int e4 = t; e4 < EE / 4; e4 += 512) {
        int4 s = src4[e4], d = dst4[e4];
        int ss[4] = {s.x, s.y, s.z, s.w};
        int dd[4] = {d.x, d.y, d.z, d.w};
#pragma unroll
        for (int k = 0; k < 4; k++) {
            if (smask[ss[k]] & smask[dd[k]]) {
                int pos = atomicAdd(&scur[dd[k]], 1);
                float2 v;
                v.x = __int_as_float(ss[k]);
                v.y = sdis[ss[k]] * sdis[dd[k]];
                csr[pos] = v;
            }
        }
    }
}

// ---------------------------------------------------------------------------
// K1: fused GCN layer. One CTA per (batch, 128-node tile), 256 threads.
//   Phase 1: CSR gather-aggregate z rows into smem (no atomics, float4 lanes,
//            2 (F=64) / 4 (F=32) edges in flight per warp).
//   Phase 2: 128xF @ Fx64 GEMM from smem + bias + mask + relu.
//   Epilogue: F==32 -> write h1 to gmem;  F==64 -> accumulate pooled sums.
// ---------------------------------------------------------------------------
template <int F>
__global__ __launch_bounds__(256) void k_layer(const float* __restrict__ xin,
                                               const float* __restrict__ W,
                                               const float* __restrict__ bias,
                                               const unsigned char* __restrict__ msk) {
    constexpr int SZ = F + 4;  // padded row stride (multiple of 4 for float4)
    extern __shared__ float sm[];
    float* sz = sm;              // 128 * SZ
    float* sW = sz + 128 * SZ;   // F * 64
    float* sb = sW + F * 64;     // 64
    float* sp = sb + 64;         // 64 (layer-2 pool partials)

    const int t = threadIdx.x;
    const int b = blockIdx.x >> 4;               // 16 tiles per batch
    const size_t gnode0 = (size_t)blockIdx.x * 128;
    const int lnode0 = (blockIdx.x & 15) * 128;  // first node within batch

    for (int i = t; i < F * 64; i += 256) sW[i] = W[i];
    if (t < 64) {
        sb[t] = bias[t];
        if (F == 64) sp[t] = 0.f;
    }

    const float* hb = (F == 32) ? xin + (size_t)b * NN * 32
                                : (const float*)g_h + (size_t)b * NN * 64;
    const float2* csr = g_csr + (size_t)b * EE;
    const int* rp = g_rowptr + (size_t)b * (NN + 1);
    const float* dis = g_dis + (size_t)b * NN;

    const int warp = t >> 5, lane = t & 31;

    // ---- Phase 1: gather-aggregate ----
    if (F == 64) {
        const int g = lane >> 4, cl = lane & 15;  // 2 groups x 16 lanes x float4
#pragma unroll 1
        for (int k = 0; k < 16; k++) {
            const int li = warp * 16 + k;
            const int i = lnode0 + li;
            const int r0 = rp[i], r1 = rp[i + 1];
            float4 acc = make_float4(0.f, 0.f, 0.f, 0.f);
            if (g == 0) {
                float di = dis[i];
                float s = di * di;
                float4 hv = *(const float4*)(hb + (size_t)i * 64 + cl * 4);
                acc.x = s * hv.x; acc.y = s * hv.y; acc.z = s * hv.z; acc.w = s * hv.w;
            }
            for (int e = r0 + g; e < r1; e += 2) {
                float2 c = csr[e];
                const float4 gv = *(const float4*)(hb + (size_t)__float_as_int(c.x) * 64 + cl * 4);
                acc.x = fmaf(c.y, gv.x, acc.x);
                acc.y = fmaf(c.y, gv.y, acc.y);
                acc.z = fmaf(c.y, gv.z, acc.z);
                acc.w = fmaf(c.y, gv.w, acc.w);
            }
            acc.x += __shfl_xor_sync(0xffffffffu, acc.x, 16);
            acc.y += __shfl_xor_sync(0xffffffffu, acc.y, 16);
            acc.z += __shfl_xor_sync(0xffffffffu, acc.z, 16);
            acc.w += __shfl_xor_sync(0xffffffffu, acc.w, 16);
            if (g == 0) *(float4*)(sz + li * SZ + cl * 4) = acc;
        }
    } else {
        const int g = lane >> 3, cl = lane & 7;  // 4 groups x 8 lanes x float4
#pragma unroll 1
        for (int k = 0; k < 16; k++) {
            const int li = warp * 16 + k;
            const int i = lnode0 + li;
            const int r0 = rp[i], r1 = rp[i + 1];
            float4 acc = make_float4(0.f, 0.f, 0.f, 0.f);
            if (g == 0) {
                float di = dis[i];
                float s = di * di;
                float4 hv = *(const float4*)(hb + (size_t)i * 32 + cl * 4);
                acc.x = s * hv.x; acc.y = s * hv.y; acc.z = s * hv.z; acc.w = s * hv.w;
            }
            for (int e = r0 + g; e < r1; e += 4) {
                float2 c = csr[e];
                const float4 gv = *(const float4*)(hb + (size_t)__float_as_int(c.x) * 32 + cl * 4);
                acc.x = fmaf(c.y, gv.x, acc.x);
                acc.y = fmaf(c.y, gv.y, acc.y);
                acc.z = fmaf(c.y, gv.z, acc.z);
                acc.w = fmaf(c.y, gv.w, acc.w);
            }
            acc.x += __shfl_xor_sync(0xffffffffu, acc.x, 8);
            acc.y += __shfl_xor_sync(0xffffffffu, acc.y, 8);
            acc.z += __shfl_xor_sync(0xffffffffu, acc.z, 8);
            acc.w += __shfl_xor_sync(0xffffffffu, acc.w, 8);
            acc.x += __shfl_xor_sync(0xffffffffu, acc.x, 16);
            acc.y += __shfl_xor_sync(0xffffffffu, acc.y, 16);
            acc.z += __shfl_xor_sync(0xffffffffu, acc.z, 16);
            acc.w += __shfl_xor_sync(0xffffffffu, acc.w, 16);
            if (g == 0) *(float4*)(sz + li * SZ + cl * 4) = acc;
        }
    }
    __syncthreads();

    // ---- Phase 2: GEMM (each thread: 2 nodes x 16 channels) ----
    const int cg = t & 3;     // channel group (16 ch)
    const int ng = t >> 2;    // node slot 0..63 (rows ng and ng+64)
    const bool wide = mask_is_wide(msk);

    float acc[2][16];
#pragma unroll
    for (int k = 0; k < 2; k++)
#pragma unroll
        for (int j = 0; j < 16; j++) acc[k][j] = 0.f;

    for (int f = 0; f < F; f += 4) {
        float4 z0 = *(const float4*)(sz + ng * SZ + f);
        float4 z1 = *(const float4*)(sz + (ng + 64) * SZ + f);
        float zr0[4] = {z0.x, z0.y, z0.z, z0.w};
        float zr1[4] = {z1.x, z1.y, z1.z, z1.w};
#pragma unroll
        for (int ff = 0; ff < 4; ff++) {
            float wv[16];
            const float4* wr = (const float4*)(sW + (f + ff) * 64 + cg * 16);
            *(float4*)&wv[0]  = wr[0];
            *(float4*)&wv[4]  = wr[1];
            *(float4*)&wv[8]  = wr[2];
            *(float4*)&wv[12] = wr[3];
#pragma unroll
            for (int j = 0; j < 16; j++) {
                acc[0][j] = fmaf(zr0[ff], wv[j], acc[0][j]);
                acc[1][j] = fmaf(zr1[ff], wv[j], acc[1][j]);
            }
        }
    }

    // ---- Epilogue ----
    if (F == 32) {
        // layer 1: h1 = relu((z@W1 + b1) * mask) -> gmem
#pragma unroll
        for (int k = 0; k < 2; k++) {
            size_t gn = gnode0 + ng + 64 * k;
            float m = mask_at(msk, wide, gn) ? 1.f : 0.f;
            float* outp = g_h + gn * 64 + cg * 16;
#pragma unroll
            for (int q = 0; q < 4; q++) {
                float4 o;
                o.x = fmaxf((acc[k][q * 4 + 0] + sb[cg * 16 + q * 4 + 0]) * m, 0.f);
                o.y = fmaxf((acc[k][q * 4 + 1] + sb[cg * 16 + q * 4 + 1]) * m, 0.f);
                o.z = fmaxf((acc[k][q * 4 + 2] + sb[cg * 16 + q * 4 + 2]) * m, 0.f);
                o.w = fmaxf((acc[k][q * 4 + 3] + sb[cg * 16 + q * 4 + 3]) * m, 0.f);
                ((float4*)outp)[q] = o;
            }
        }
    } else {
        // layer 2: h2 feeds only pooling -> accumulate sum over nodes
        float ps[16];
#pragma unroll
        for (int j = 0; j < 16; j++) ps[j] = 0.f;
#pragma unroll
        for (int k = 0; k < 2; k++) {
            size_t gn = gnode0 + ng + 64 * k;
            float m = mask_at(msk, wide, gn) ? 1.f : 0.f;
#pragma unroll
            for (int j = 0; j < 16; j++)
                ps[j] += fmaxf((acc[k][j] + sb[cg * 16 + j]) * m, 0.f);
        }
        // butterfly over node-group lanes (bits 2..4) — all lanes share cg
#pragma unroll
        for (int j = 0; j < 16; j++) {
            float v = ps[j];
            v += __shfl_xor_sync(0xffffffffu, v, 4);
            v += __shfl_xor_sync(0xffffffffu, v, 8);
            v += __shfl_xor_sync(0xffffffffu, v, 16);
            ps[j] = v;
        }
        if (lane < 4) {  // lane == cg for these lanes
#pragma unroll
            for (int j = 0; j < 16; j++) atomicAdd(&sp[lane * 16 + j], ps[j]);
        }
        __syncthreads();
        if (t < 64) atomicAdd(&g_pool[b * 64 + t], sp[t]);
    }
}

// ---------------------------------------------------------------------------
// K2: finish pooling (divide by n) + 2-layer MLP head, one CTA per batch
// ---------------------------------------------------------------------------
__global__ __launch_bounds__(64) void k_pool(const float* __restrict__ aW1,
                                             const float* __restrict__ ab1,
                                             const float* __restrict__ aW2,
                                             const float* __restrict__ ab2,
                                             float* __restrict__ out) {
    __shared__ float pooled[64];
    __shared__ float hid[64];
    const int b = blockIdx.x, t = threadIdx.x;
    int n = g_n[b];
    if (n < 1) n = 1;
    pooled[t] = g_pool[b * 64 + t] / (float)n;
    __syncthreads();
    {
        float a = ab1[t];
#pragma unroll
        for (int f = 0; f < 64; f++) a = fmaf(pooled[f], aW1[f * 64 + t], a);
        hid[t] = fmaxf(a, 0.f);
    }
    __syncthreads();
    if (t < 16) {
        float a = ab2[t];
#pragma unroll
        for (int f = 0; f < 64; f++) a = fmaf(hid[f], aW2[f * 16 + t], a);
        out[b * 16 + t] = a;
    }
}

// ---------------------------------------------------------------------------
extern "C" void kernel_launch(void* const* d_in, const int* in_sizes, int n_in,
                              void* d_out, int out_size) {
    const float*         x   = (const float*)d_in[0];
    const int*           ei  = (const int*)d_in[1];
    const unsigned char* msk = (const unsigned char*)d_in[2];
    const float* W1  = (const float*)d_in[3];
    const float* b1  = (const float*)d_in[4];
    const float* W2  = (const float*)d_in[5];
    const float* b2  = (const float*)d_in[6];
    const float* aW1 = (const float*)d_in[7];
    const float* ab1 = (const float*)d_in[8];
    const float* aW2 = (const float*)d_in[9];
    const float* ab2 = (const float*)d_in[10];
    float* out = (float*)d_out;

    const int sm32 = (128 * 36 + 32 * 64 + 64 + 64) * 4;  // ~26.5 KB
    const int sm64 = (128 * 68 + 64 * 64 + 64 + 64) * 4;  // ~50.5 KB
    cudaFuncSetAttribute(k_layer<32>, cudaFuncAttributeMaxDynamicSharedMemorySize, sm32);
    cudaFuncSetAttribute(k_layer<64>, cudaFuncAttributeMaxDynamicSharedMemorySize, sm64);

    // prep: degrees, dis, CSR with per-edge norm (invalid edges dropped), zero pools
    k_prep<<<BB, 512>>>(ei, msk);
    // layer 1 fused: gather(x) -> GEMM(W1) -> h1
    k_layer<32><<<(BB * NN) / 128, 256, sm32>>>(x, W1, b1, msk);
    // layer 2 fused: gather(h1) -> GEMM(W2) -> pooled partial sums
    k_layer<64><<<(BB * NN) / 128, 256, sm64>>>(x, W2, b2, msk);
    // finish pool + MLP head
    k_pool<<<BB, 64>>>(aW1, ab1, aW2, ab2, out);
}